// round 3
// baseline (speedup 1.0000x reference)
#include <cuda_runtime.h>
#include <math.h>

#define Bb 64
#define Nn 3
#define Tt 4096
#define Dd 64
#define Hh 128
#define ROWS ((size_t)Bb * Nn * Tt)   // 786432

typedef unsigned long long u64;

// -------- packed f32x2 helpers (Blackwell fma.rn.f32x2) --------
__device__ __forceinline__ u64 pk(float lo, float hi) {
    u64 r; asm("mov.b64 %0,{%1,%2};" : "=l"(r) : "f"(lo), "f"(hi)); return r;
}
__device__ __forceinline__ void upk(u64 v, float& lo, float& hi) {
    asm("mov.b64 {%0,%1},%2;" : "=f"(lo), "=f"(hi) : "l"(v));
}
__device__ __forceinline__ u64 f2fma(u64 a, u64 b, u64 c) {
    u64 d; asm("fma.rn.f32x2 %0,%1,%2,%3;" : "=l"(d) : "l"(a), "l"(b), "l"(c)); return d;
}
__device__ __forceinline__ float fex2(float x) {
    float r; asm("ex2.approx.f32 %0,%1;" : "=f"(r) : "f"(x)); return r;
}
__device__ __forceinline__ float frcp(float x) {
    float r; asm("rcp.approx.f32 %0,%1;" : "=f"(r) : "f"(x)); return r;
}
#define LOG2E 1.4426950408889634f
__device__ __forceinline__ float fsig(float x) { return frcp(1.f + fex2(-x * LOG2E)); }
__device__ __forceinline__ float ftanh_f(float x) { return 1.f - 2.f * frcp(1.f + fex2(x * (2.f * LOG2E))); }

// -------- scratch (static device globals; no runtime allocation) --------
__device__ float g_h  [(size_t)Bb * Nn * Tt * Hh];
__device__ float g_hsp[(size_t)Bb * Nn * Tt * Hh];
__device__ float g_gx [(size_t)Bb * Nn * Tt * 3 * Hh];

// ============================================================
// Kernel A: h = x @ gat_W + gat_b      (786432 x 64) @ (64 x 128)  [f32x2]
// ============================================================
__global__ __launch_bounds__(128) void gat_kernel(const float* __restrict__ x,
                                                  const float* __restrict__ W,
                                                  const float* __restrict__ bias)
{
    __shared__ __align__(16) float xs[16][64];
    const int c = threadIdx.x;
    const size_t r0 = (size_t)blockIdx.x * 16;

    {
        const float4* src = (const float4*)(x + r0 * Dd);
        float4* dst = (float4*)xs;
        dst[c]       = src[c];
        dst[c + 128] = src[c + 128];
    }
    u64 w2[32];
#pragma unroll
    for (int i = 0; i < 32; i++)
        w2[i] = pk(W[(2 * i) * Hh + c], W[(2 * i + 1) * Hh + c]);
    const float bv = bias[c];
    __syncthreads();

#pragma unroll 4
    for (int r = 0; r < 16; r++) {
        const ulonglong2* xr = (const ulonglong2*)xs[r];
        u64 a0 = 0ull, a1 = 0ull;
#pragma unroll
        for (int i = 0; i < 16; i++) {
            ulonglong2 xv = xr[i];
            a0 = f2fma(xv.x, w2[2 * i],     a0);
            a1 = f2fma(xv.y, w2[2 * i + 1], a1);
        }
        float l0, h0, l1, h1; upk(a0, l0, h0); upk(a1, l1, h1);
        g_h[(r0 + r) * Hh + c] = (l0 + h0) + (l1 + h1) + bv;
    }
}

// ============================================================
// Kernel B: attention + softmax + ELU + spatial LayerNorm
// ============================================================
__global__ __launch_bounds__(128) void attn_kernel(const float* __restrict__ a_src,
                                                   const float* __restrict__ a_dst,
                                                   const float* __restrict__ abias,
                                                   const float* __restrict__ sng,
                                                   const float* __restrict__ snb)
{
    const int c = threadIdx.x;
    const int warp = c >> 5, lane = c & 31;
    const int b = blockIdx.y;
    const int t0 = blockIdx.x * 4;

    __shared__ float red1[4][6];
    __shared__ float red2[4][6];

    const float asv = a_src[c], adv = a_dst[c];
    const float gw = sng[c], gb = snb[c];
    float bi[9];
#pragma unroll
    for (int q = 0; q < 9; q++) bi[q] = abias[q];

    for (int tt = 0; tt < 4; tt++) {
        const int t = t0 + tt;
        float hv[3];
#pragma unroll
        for (int j = 0; j < 3; j++)
            hv[j] = g_h[(((size_t)b * Nn + j) * Tt + t) * Hh + c];

        float p[6];
        p[0] = hv[0] * asv; p[1] = hv[1] * asv; p[2] = hv[2] * asv;
        p[3] = hv[0] * adv; p[4] = hv[1] * adv; p[5] = hv[2] * adv;
#pragma unroll
        for (int off = 16; off; off >>= 1) {
#pragma unroll
            for (int q = 0; q < 6; q++)
                p[q] += __shfl_xor_sync(0xffffffffu, p[q], off);
        }
        if (lane == 0) {
#pragma unroll
            for (int q = 0; q < 6; q++) red1[warp][q] = p[q];
        }
        __syncthreads();
        float ss[3], sd[3];
#pragma unroll
        for (int j = 0; j < 3; j++) {
            ss[j] = red1[0][j] + red1[1][j] + red1[2][j] + red1[3][j];
            sd[j] = red1[0][3 + j] + red1[1][3 + j] + red1[2][3 + j] + red1[3][3 + j];
        }

        float o[3];
#pragma unroll
        for (int i = 0; i < 3; i++) {
            float sc[3];
#pragma unroll
            for (int j = 0; j < 3; j++) {
                float v = ss[i] + sd[j];
                v = v > 0.f ? v : 0.2f * v;
                sc[j] = v + bi[i * 3 + j];
            }
            float mx = fmaxf(sc[0], fmaxf(sc[1], sc[2]));
            float e0 = __expf(sc[0] - mx), e1 = __expf(sc[1] - mx), e2 = __expf(sc[2] - mx);
            float inv = frcp(e0 + e1 + e2);
            float ov = (e0 * hv[0] + e1 * hv[1] + e2 * hv[2]) * inv;
            o[i] = ov > 0.f ? ov : (__expf(ov) - 1.f);
        }

        float q2[6] = { o[0], o[0]*o[0], o[1], o[1]*o[1], o[2], o[2]*o[2] };
#pragma unroll
        for (int off = 16; off; off >>= 1) {
#pragma unroll
            for (int q = 0; q < 6; q++)
                q2[q] += __shfl_xor_sync(0xffffffffu, q2[q], off);
        }
        if (lane == 0) {
#pragma unroll
            for (int q = 0; q < 6; q++) red2[warp][q] = q2[q];
        }
        __syncthreads();
#pragma unroll
        for (int i = 0; i < 3; i++) {
            float s  = red2[0][2*i]   + red2[1][2*i]   + red2[2][2*i]   + red2[3][2*i];
            float sq = red2[0][2*i+1] + red2[1][2*i+1] + red2[2][2*i+1] + red2[3][2*i+1];
            float mean = s * (1.f / Hh);
            float var  = sq * (1.f / Hh) - mean * mean;
            float rstd = rsqrtf(var + 1e-5f);
            g_hsp[(((size_t)b * Nn + i) * Tt + t) * Hh + c] = (o[i] - mean) * rstd * gw + gb;
        }
    }
}

// ============================================================
// Kernel C: gx = h_sp @ W_ih^T + b_ih   [f32x2]
// ============================================================
__global__ __launch_bounds__(256) void gx_kernel(const float* __restrict__ Wih,
                                                 const float* __restrict__ bih)
{
    __shared__ __align__(16) float hs[32][128];
    __shared__ float ws[128][33];

    const int tid = threadIdx.x;
    const int gg  = tid & 127;
    const int rh  = tid >> 7;
    const int g0  = blockIdx.y * 128;
    const size_t r0 = (size_t)blockIdx.x * 32;

    {
        const float4* src = (const float4*)(g_hsp + r0 * Hh);
        float4* dst = (float4*)hs;
#pragma unroll
        for (int i = 0; i < 4; i++) dst[tid + 256 * i] = src[tid + 256 * i];
    }

    u64 acc[16];
#pragma unroll
    for (int i = 0; i < 16; i++) acc[i] = 0ull;

    for (int p = 0; p < 4; p++) {
        if (p) __syncthreads();
#pragma unroll
        for (int i = 0; i < 16; i++) {
            int idx = tid + 256 * i;
            int row = idx >> 5, k = idx & 31;
            ws[row][k] = Wih[(size_t)(g0 + row) * Hh + p * 32 + k];
        }
        __syncthreads();

        u64 w2[16];
#pragma unroll
        for (int i = 0; i < 16; i++)
            w2[i] = pk(ws[gg][2 * i], ws[gg][2 * i + 1]);

#pragma unroll
        for (int r = 0; r < 16; r++) {
            const ulonglong2* xr = (const ulonglong2*)(hs[rh * 16 + r] + p * 32);
#pragma unroll
            for (int i = 0; i < 8; i++) {
                ulonglong2 xv = xr[i];
                acc[r] = f2fma(xv.x, w2[2 * i],     acc[r]);
                acc[r] = f2fma(xv.y, w2[2 * i + 1], acc[r]);
            }
        }
    }

    const float bv = bih[g0 + gg];
#pragma unroll
    for (int r = 0; r < 16; r++) {
        size_t row = r0 + rh * 16 + r;
        float lo, hi; upk(acc[r], lo, hi);
        g_gx[row * 384 + g0 + gg] = lo + hi + bv;
    }
}

// ============================================================
// Kernel D: GRU. 96 blocks x 384 threads; 2 sequences per block.
// Thread u owns K-half (u/192) of rows {rbase, rbase+192}: 128 weight regs.
// Partials packed (seqA,seqB) in u64; gates read 6 LDS.32; gx staged via smem.
// ============================================================
__global__ __launch_bounds__(384, 1) void gru_kernel(const float* __restrict__ Whh,
                                                     const float* __restrict__ bhh,
                                                     float* __restrict__ out)
{
    const int u = threadIdx.x;                  // 0..383
    const int sA = blockIdx.x * 2;

    const int half  = (u >= 192) ? 1 : 0;
    const int rbase = u - half * 192;           // 0..191
    const int r1 = rbase, r2 = rbase + 192;

    __shared__ __align__(16) float hbuf[2][128];
    __shared__ u64  px[2][384];                 // [half][row] -> (partA, partB)
    __shared__ float gxs[2][384];               // [seq][gate-row], current step

    // register-resident weights: K-half of rows r1 and r2 (64 floats each)
    u64 w1[32], w2r[32];
    {
        const u64* p1 = (const u64*)(Whh + (size_t)r1 * Hh + half * 64);
        const u64* p2 = (const u64*)(Whh + (size_t)r2 * Hh + half * 64);
#pragma unroll
        for (int i = 0; i < 32; i++) { w1[i] = p1[i]; w2r[i] = p2[i]; }
    }
    // bias folded into half-0 partials only
    const float bh1 = half ? 0.f : bhh[r1];
    const float bh2 = half ? 0.f : bhh[r2];

    const int gq = u & 127, gs = u >> 7;        // gate mapping (u < 256)

    if (u < 128) { hbuf[0][u] = 0.f; hbuf[1][u] = 0.f; }

    const float* gA = g_gx + (size_t)sA * Tt * 384;
    const float* gB = gA + (size_t)Tt * 384;
    float* opA = out + (size_t)sA * Tt * Hh;
    float* opB = opA + (size_t)Tt * Hh;
    const float* pxf = (const float*)px;        // float view: [(h*384+row)*2 + seq]
    __syncthreads();

    for (int t = 0; t < Tt; t++) {
        // stage this step's input gates into shared (consumed after bar1)
        gxs[0][u] = __ldg(gA + (size_t)t * 384 + u);
        gxs[1][u] = __ldg(gB + (size_t)t * 384 + u);

        // hidden matvec partials over this thread's K-half
        const ulonglong2* hA2 = (const ulonglong2*)(hbuf[0] + half * 64);
        const ulonglong2* hB2 = (const ulonglong2*)(hbuf[1] + half * 64);
        u64 a1A = 0ull, a2A = 0ull, a1B = 0ull, a2B = 0ull;
#pragma unroll
        for (int i = 0; i < 16; i++) {
            ulonglong2 ha = hA2[i];
            ulonglong2 hb = hB2[i];
            a1A = f2fma(w1[2*i],    ha.x, a1A);
            a2A = f2fma(w2r[2*i],   ha.x, a2A);
            a1B = f2fma(w1[2*i],    hb.x, a1B);
            a2B = f2fma(w2r[2*i],   hb.x, a2B);
            a1A = f2fma(w1[2*i+1],  ha.y, a1A);
            a2A = f2fma(w2r[2*i+1], ha.y, a2A);
            a1B = f2fma(w1[2*i+1],  hb.y, a1B);
            a2B = f2fma(w2r[2*i+1], hb.y, a2B);
        }
        float lo, hi;
        upk(a1A, lo, hi); const float p1A = lo + hi + bh1;
        upk(a2A, lo, hi); const float p2A = lo + hi + bh2;
        upk(a1B, lo, hi); const float p1B = lo + hi + bh1;
        upk(a2B, lo, hi); const float p2B = lo + hi + bh2;
        px[half][r1] = pk(p1A, p1B);
        px[half][r2] = pk(p2A, p2B);
        __syncthreads();

        if (u < 256) {
            // hidden-gate sums for (seq gs, unit gq)
            const float ghr = pxf[(gq       ) * 2 + gs] + pxf[(384 + gq       ) * 2 + gs];
            const float ghz = pxf[(gq + 128 ) * 2 + gs] + pxf[(384 + gq + 128 ) * 2 + gs];
            const float ghn = pxf[(gq + 256 ) * 2 + gs] + pxf[(384 + gq + 256 ) * 2 + gs];
            const float r = fsig(gxs[gs][gq]       + ghr);
            const float z = fsig(gxs[gs][gq + 128] + ghz);
            const float n = ftanh_f(gxs[gs][gq + 256] + r * ghn);
            const float hp = hbuf[gs][gq];
            const float hnew = (1.f - z) * n + z * hp;
            hbuf[gs][gq] = hnew;
            (gs ? opB : opA)[(size_t)t * Hh + gq] = hnew;
        }
        __syncthreads();
    }
}

// ============================================================
// Kernel E: temporal LayerNorm, in-place. One warp per row.
// ============================================================
__global__ __launch_bounds__(256) void tln_kernel(float* __restrict__ out,
                                                  const float* __restrict__ g,
                                                  const float* __restrict__ b)
{
    const int warp = threadIdx.x >> 5, lane = threadIdx.x & 31;
    const size_t row = (size_t)blockIdx.x * 8 + warp;
    float4* p = (float4*)(out + row * Hh);
    float4 v = p[lane];
    float s = v.x + v.y + v.z + v.w;
    float q = v.x * v.x + v.y * v.y + v.z * v.z + v.w * v.w;
#pragma unroll
    for (int off = 16; off; off >>= 1) {
        s += __shfl_xor_sync(0xffffffffu, s, off);
        q += __shfl_xor_sync(0xffffffffu, q, off);
    }
    const float mean = s * (1.f / Hh);
    const float var  = q * (1.f / Hh) - mean * mean;
    const float rstd = rsqrtf(var + 1e-5f);
    const float4 gv = ((const float4*)g)[lane];
    const float4 bv = ((const float4*)b)[lane];
    v.x = (v.x - mean) * rstd * gv.x + bv.x;
    v.y = (v.y - mean) * rstd * gv.y + bv.y;
    v.z = (v.z - mean) * rstd * gv.z + bv.z;
    v.w = (v.w - mean) * rstd * gv.w + bv.w;
    p[lane] = v;
}

// ============================================================
extern "C" void kernel_launch(void* const* d_in, const int* in_sizes, int n_in,
                              void* d_out, int out_size)
{
    const float* x      = (const float*)d_in[0];
    const float* gat_W  = (const float*)d_in[1];
    const float* gat_b  = (const float*)d_in[2];
    const float* a_src  = (const float*)d_in[3];
    const float* a_dst  = (const float*)d_in[4];
    const float* abias  = (const float*)d_in[5];
    const float* sn_g   = (const float*)d_in[6];
    const float* sn_b   = (const float*)d_in[7];
    const float* W_ih   = (const float*)d_in[8];
    const float* W_hh   = (const float*)d_in[9];
    const float* b_ih   = (const float*)d_in[10];
    const float* b_hh   = (const float*)d_in[11];
    const float* tn_g   = (const float*)d_in[12];
    const float* tn_b   = (const float*)d_in[13];
    float* out = (float*)d_out;

    gat_kernel<<<ROWS / 16, 128>>>(x, gat_W, gat_b);
    attn_kernel<<<dim3(Tt / 4, Bb), 128>>>(a_src, a_dst, abias, sn_g, sn_b);
    gx_kernel<<<dim3(ROWS / 32, 3), 256>>>(W_ih, b_ih);
    gru_kernel<<<Bb * Nn / 2, 384>>>(W_hh, b_hh, out);
    tln_kernel<<<ROWS / 8, 256>>>(out, tn_g, tn_b);
}

// round 4
// speedup vs baseline: 1.1602x; 1.1602x over previous
#include <cuda_runtime.h>
#include <math.h>

#define Bb 64
#define Nn 3
#define Tt 4096
#define Dd 64
#define Hh 128
#define ROWS ((size_t)Bb * Nn * Tt)   // 786432

typedef unsigned long long u64;

// -------- packed f32x2 helpers (Blackwell fma.rn.f32x2) --------
__device__ __forceinline__ u64 pk(float lo, float hi) {
    u64 r; asm("mov.b64 %0,{%1,%2};" : "=l"(r) : "f"(lo), "f"(hi)); return r;
}
__device__ __forceinline__ void upk(u64 v, float& lo, float& hi) {
    asm("mov.b64 {%0,%1},%2;" : "=f"(lo), "=f"(hi) : "l"(v));
}
__device__ __forceinline__ u64 f2fma(u64 a, u64 b, u64 c) {
    u64 d; asm("fma.rn.f32x2 %0,%1,%2,%3;" : "=l"(d) : "l"(a), "l"(b), "l"(c)); return d;
}
__device__ __forceinline__ float fex2(float x) {
    float r; asm("ex2.approx.f32 %0,%1;" : "=f"(r) : "f"(x)); return r;
}
__device__ __forceinline__ float frcp(float x) {
    float r; asm("rcp.approx.f32 %0,%1;" : "=f"(r) : "f"(x)); return r;
}
#define LOG2E 1.4426950408889634f
__device__ __forceinline__ float fsig(float x) { return frcp(1.f + fex2(-x * LOG2E)); }
__device__ __forceinline__ float ftanh_f(float x) { return 1.f - 2.f * frcp(1.f + fex2(x * (2.f * LOG2E))); }

// -------- scratch (static device globals; no runtime allocation) --------
__device__ float g_h  [(size_t)Bb * Nn * Tt * Hh];
__device__ float g_hsp[(size_t)Bb * Nn * Tt * Hh];
__device__ float g_gx [(size_t)Bb * Nn * Tt * 3 * Hh];

// ============================================================
// Kernel A: h = x @ gat_W + gat_b      (786432 x 64) @ (64 x 128)  [f32x2]
// ============================================================
__global__ __launch_bounds__(128) void gat_kernel(const float* __restrict__ x,
                                                  const float* __restrict__ W,
                                                  const float* __restrict__ bias)
{
    __shared__ __align__(16) float xs[16][64];
    const int c = threadIdx.x;
    const size_t r0 = (size_t)blockIdx.x * 16;

    {
        const float4* src = (const float4*)(x + r0 * Dd);
        float4* dst = (float4*)xs;
        dst[c]       = src[c];
        dst[c + 128] = src[c + 128];
    }
    u64 w2[32];
#pragma unroll
    for (int i = 0; i < 32; i++)
        w2[i] = pk(W[(2 * i) * Hh + c], W[(2 * i + 1) * Hh + c]);
    const float bv = bias[c];
    __syncthreads();

#pragma unroll 4
    for (int r = 0; r < 16; r++) {
        const ulonglong2* xr = (const ulonglong2*)xs[r];
        u64 a0 = 0ull, a1 = 0ull;
#pragma unroll
        for (int i = 0; i < 16; i++) {
            ulonglong2 xv = xr[i];
            a0 = f2fma(xv.x, w2[2 * i],     a0);
            a1 = f2fma(xv.y, w2[2 * i + 1], a1);
        }
        float l0, h0, l1, h1; upk(a0, l0, h0); upk(a1, l1, h1);
        g_h[(r0 + r) * Hh + c] = (l0 + h0) + (l1 + h1) + bv;
    }
}

// ============================================================
// Kernel B: attention + softmax + ELU + spatial LayerNorm
// ============================================================
__global__ __launch_bounds__(128) void attn_kernel(const float* __restrict__ a_src,
                                                   const float* __restrict__ a_dst,
                                                   const float* __restrict__ abias,
                                                   const float* __restrict__ sng,
                                                   const float* __restrict__ snb)
{
    const int c = threadIdx.x;
    const int warp = c >> 5, lane = c & 31;
    const int b = blockIdx.y;
    const int t0 = blockIdx.x * 4;

    __shared__ float red1[4][6];
    __shared__ float red2[4][6];

    const float asv = a_src[c], adv = a_dst[c];
    const float gw = sng[c], gb = snb[c];
    float bi[9];
#pragma unroll
    for (int q = 0; q < 9; q++) bi[q] = abias[q];

    for (int tt = 0; tt < 4; tt++) {
        const int t = t0 + tt;
        float hv[3];
#pragma unroll
        for (int j = 0; j < 3; j++)
            hv[j] = g_h[(((size_t)b * Nn + j) * Tt + t) * Hh + c];

        float p[6];
        p[0] = hv[0] * asv; p[1] = hv[1] * asv; p[2] = hv[2] * asv;
        p[3] = hv[0] * adv; p[4] = hv[1] * adv; p[5] = hv[2] * adv;
#pragma unroll
        for (int off = 16; off; off >>= 1) {
#pragma unroll
            for (int q = 0; q < 6; q++)
                p[q] += __shfl_xor_sync(0xffffffffu, p[q], off);
        }
        if (lane == 0) {
#pragma unroll
            for (int q = 0; q < 6; q++) red1[warp][q] = p[q];
        }
        __syncthreads();
        float ss[3], sd[3];
#pragma unroll
        for (int j = 0; j < 3; j++) {
            ss[j] = red1[0][j] + red1[1][j] + red1[2][j] + red1[3][j];
            sd[j] = red1[0][3 + j] + red1[1][3 + j] + red1[2][3 + j] + red1[3][3 + j];
        }

        float o[3];
#pragma unroll
        for (int i = 0; i < 3; i++) {
            float sc[3];
#pragma unroll
            for (int j = 0; j < 3; j++) {
                float v = ss[i] + sd[j];
                v = v > 0.f ? v : 0.2f * v;
                sc[j] = v + bi[i * 3 + j];
            }
            float mx = fmaxf(sc[0], fmaxf(sc[1], sc[2]));
            float e0 = __expf(sc[0] - mx), e1 = __expf(sc[1] - mx), e2 = __expf(sc[2] - mx);
            float inv = frcp(e0 + e1 + e2);
            float ov = (e0 * hv[0] + e1 * hv[1] + e2 * hv[2]) * inv;
            o[i] = ov > 0.f ? ov : (__expf(ov) - 1.f);
        }

        float q2[6] = { o[0], o[0]*o[0], o[1], o[1]*o[1], o[2], o[2]*o[2] };
#pragma unroll
        for (int off = 16; off; off >>= 1) {
#pragma unroll
            for (int q = 0; q < 6; q++)
                q2[q] += __shfl_xor_sync(0xffffffffu, q2[q], off);
        }
        if (lane == 0) {
#pragma unroll
            for (int q = 0; q < 6; q++) red2[warp][q] = q2[q];
        }
        __syncthreads();
#pragma unroll
        for (int i = 0; i < 3; i++) {
            float s  = red2[0][2*i]   + red2[1][2*i]   + red2[2][2*i]   + red2[3][2*i];
            float sq = red2[0][2*i+1] + red2[1][2*i+1] + red2[2][2*i+1] + red2[3][2*i+1];
            float mean = s * (1.f / Hh);
            float var  = sq * (1.f / Hh) - mean * mean;
            float rstd = rsqrtf(var + 1e-5f);
            g_hsp[(((size_t)b * Nn + i) * Tt + t) * Hh + c] = (o[i] - mean) * rstd * gw + gb;
        }
    }
}

// ============================================================
// Kernel C: gx = h_sp @ W_ih^T + b_ih   [f32x2]
// ============================================================
__global__ __launch_bounds__(256) void gx_kernel(const float* __restrict__ Wih,
                                                 const float* __restrict__ bih)
{
    __shared__ __align__(16) float hs[32][128];
    __shared__ float ws[128][33];

    const int tid = threadIdx.x;
    const int gg  = tid & 127;
    const int rh  = tid >> 7;
    const int g0  = blockIdx.y * 128;
    const size_t r0 = (size_t)blockIdx.x * 32;

    {
        const float4* src = (const float4*)(g_hsp + r0 * Hh);
        float4* dst = (float4*)hs;
#pragma unroll
        for (int i = 0; i < 4; i++) dst[tid + 256 * i] = src[tid + 256 * i];
    }

    u64 acc[16];
#pragma unroll
    for (int i = 0; i < 16; i++) acc[i] = 0ull;

    for (int p = 0; p < 4; p++) {
        if (p) __syncthreads();
#pragma unroll
        for (int i = 0; i < 16; i++) {
            int idx = tid + 256 * i;
            int row = idx >> 5, k = idx & 31;
            ws[row][k] = Wih[(size_t)(g0 + row) * Hh + p * 32 + k];
        }
        __syncthreads();

        u64 w2[16];
#pragma unroll
        for (int i = 0; i < 16; i++)
            w2[i] = pk(ws[gg][2 * i], ws[gg][2 * i + 1]);

#pragma unroll
        for (int r = 0; r < 16; r++) {
            const ulonglong2* xr = (const ulonglong2*)(hs[rh * 16 + r] + p * 32);
#pragma unroll
            for (int i = 0; i < 8; i++) {
                ulonglong2 xv = xr[i];
                acc[r] = f2fma(xv.x, w2[2 * i],     acc[r]);
                acc[r] = f2fma(xv.y, w2[2 * i + 1], acc[r]);
            }
        }
    }

    const float bv = bih[g0 + gg];
#pragma unroll
    for (int r = 0; r < 16; r++) {
        size_t row = r0 + rh * 16 + r;
        float lo, hi; upk(acc[r], lo, hi);
        g_gx[row * 384 + g0 + gg] = lo + hi + bv;
    }
}

// ============================================================
// Kernel D: GRU. 96 blocks x 384 threads; 2 sequences per block.
// K-split: thread u owns K-half (u>=192) of rows {rbase, rbase+192}.
// Gate threads (u<256) prefetch their own 3 gx values one step ahead
// into registers -> zero LDG-dependent stalls inside the step.
// ============================================================
__global__ __launch_bounds__(384, 1) void gru_kernel(const float* __restrict__ Whh,
                                                     const float* __restrict__ bhh,
                                                     float* __restrict__ out)
{
    const int u = threadIdx.x;                  // 0..383
    const int sA = blockIdx.x * 2;

    const int half  = (u >= 192) ? 1 : 0;
    const int rbase = u - half * 192;           // 0..191
    const int r1 = rbase, r2 = rbase + 192;

    __shared__ __align__(16) float hbuf[2][128];
    __shared__ u64 px[2][384];                  // [half][row] -> (partA, partB)

    // register-resident weights: K-half of rows r1 and r2 (64 floats each)
    u64 w1[32], w2r[32];
    {
        const u64* p1 = (const u64*)(Whh + (size_t)r1 * Hh + half * 64);
        const u64* p2 = (const u64*)(Whh + (size_t)r2 * Hh + half * 64);
#pragma unroll
        for (int i = 0; i < 32; i++) { w1[i] = p1[i]; w2r[i] = p2[i]; }
    }
    // bias folded into half-0 partials only
    const float bh1 = half ? 0.f : bhh[r1];
    const float bh2 = half ? 0.f : bhh[r2];

    // gate-thread mapping (valid for u < 256)
    const int gq = u & 127;
    const int gs = (u >> 7) & 1;

    if (u < 128) { hbuf[0][u] = 0.f; hbuf[1][u] = 0.f; }

    const float* gxp = g_gx + (size_t)(sA + gs) * Tt * 384;
    float* op = out + (size_t)(sA + gs) * Tt * Hh;
    const float* pxf = (const float*)px;        // float view: [(h*384+row)*2 + seq]

    // prefetch step-0 gate inputs (gate threads only)
    float fr = 0.f, fz = 0.f, fn = 0.f;
    if (u < 256) {
        fr = __ldg(gxp + gq);
        fz = __ldg(gxp + gq + 128);
        fn = __ldg(gxp + gq + 256);
    }
    __syncthreads();

    for (int t = 0; t < Tt; t++) {
        // hidden matvec partials over this thread's K-half
        const ulonglong2* hA2 = (const ulonglong2*)(hbuf[0] + half * 64);
        const ulonglong2* hB2 = (const ulonglong2*)(hbuf[1] + half * 64);
        u64 a1A = 0ull, a2A = 0ull, a1B = 0ull, a2B = 0ull;
#pragma unroll
        for (int i = 0; i < 16; i++) {
            ulonglong2 ha = hA2[i];
            ulonglong2 hb = hB2[i];
            a1A = f2fma(w1[2*i],    ha.x, a1A);
            a2A = f2fma(w2r[2*i],   ha.x, a2A);
            a1B = f2fma(w1[2*i],    hb.x, a1B);
            a2B = f2fma(w2r[2*i],   hb.x, a2B);
            a1A = f2fma(w1[2*i+1],  ha.y, a1A);
            a2A = f2fma(w2r[2*i+1], ha.y, a2A);
            a1B = f2fma(w1[2*i+1],  hb.y, a1B);
            a2B = f2fma(w2r[2*i+1], hb.y, a2B);
        }
        float lo, hi;
        upk(a1A, lo, hi); const float p1A = lo + hi + bh1;
        upk(a2A, lo, hi); const float p2A = lo + hi + bh2;
        upk(a1B, lo, hi); const float p1B = lo + hi + bh1;
        upk(a2B, lo, hi); const float p2B = lo + hi + bh2;
        px[half][r1] = pk(p1A, p1B);
        px[half][r2] = pk(p2A, p2B);
        __syncthreads();

        if (u < 256) {
            // hidden-gate sums for (seq gs, unit gq): half0 + half1 partials
            const float ghr = pxf[(gq       ) * 2 + gs] + pxf[(384 + gq       ) * 2 + gs];
            const float ghz = pxf[(gq + 128 ) * 2 + gs] + pxf[(384 + gq + 128 ) * 2 + gs];
            const float ghn = pxf[(gq + 256 ) * 2 + gs] + pxf[(384 + gq + 256 ) * 2 + gs];
            const float r = fsig(fr + ghr);
            const float z = fsig(fz + ghz);
            const float n = ftanh_f(fn + r * ghn);
            const float hp = hbuf[gs][gq];
            const float hnew = (1.f - z) * n + z * hp;
            hbuf[gs][gq] = hnew;
            op[(size_t)t * Hh + gq] = hnew;

            // prefetch next step's gx into registers (consumed next iteration;
            // ~900 cyc of cover for the load latency)
            const float* nx = gxp + (size_t)((t + 1 < Tt) ? t + 1 : t) * 384;
            fr = __ldg(nx + gq);
            fz = __ldg(nx + gq + 128);
            fn = __ldg(nx + gq + 256);
        }
        __syncthreads();
    }
}

// ============================================================
// Kernel E: temporal LayerNorm, in-place. One warp per row.
// ============================================================
__global__ __launch_bounds__(256) void tln_kernel(float* __restrict__ out,
                                                  const float* __restrict__ g,
                                                  const float* __restrict__ b)
{
    const int warp = threadIdx.x >> 5, lane = threadIdx.x & 31;
    const size_t row = (size_t)blockIdx.x * 8 + warp;
    float4* p = (float4*)(out + row * Hh);
    float4 v = p[lane];
    float s = v.x + v.y + v.z + v.w;
    float q = v.x * v.x + v.y * v.y + v.z * v.z + v.w * v.w;
#pragma unroll
    for (int off = 16; off; off >>= 1) {
        s += __shfl_xor_sync(0xffffffffu, s, off);
        q += __shfl_xor_sync(0xffffffffu, q, off);
    }
    const float mean = s * (1.f / Hh);
    const float var  = q * (1.f / Hh) - mean * mean;
    const float rstd = rsqrtf(var + 1e-5f);
    const float4 gv = ((const float4*)g)[lane];
    const float4 bv = ((const float4*)b)[lane];
    v.x = (v.x - mean) * rstd * gv.x + bv.x;
    v.y = (v.y - mean) * rstd * gv.y + bv.y;
    v.z = (v.z - mean) * rstd * gv.z + bv.z;
    v.w = (v.w - mean) * rstd * gv.w + bv.w;
    p[lane] = v;
}

// ============================================================
extern "C" void kernel_launch(void* const* d_in, const int* in_sizes, int n_in,
                              void* d_out, int out_size)
{
    const float* x      = (const float*)d_in[0];
    const float* gat_W  = (const float*)d_in[1];
    const float* gat_b  = (const float*)d_in[2];
    const float* a_src  = (const float*)d_in[3];
    const float* a_dst  = (const float*)d_in[4];
    const float* abias  = (const float*)d_in[5];
    const float* sn_g   = (const float*)d_in[6];
    const float* sn_b   = (const float*)d_in[7];
    const float* W_ih   = (const float*)d_in[8];
    const float* W_hh   = (const float*)d_in[9];
    const float* b_ih   = (const float*)d_in[10];
    const float* b_hh   = (const float*)d_in[11];
    const float* tn_g   = (const float*)d_in[12];
    const float* tn_b   = (const float*)d_in[13];
    float* out = (float*)d_out;

    gat_kernel<<<ROWS / 16, 128>>>(x, gat_W, gat_b);
    attn_kernel<<<dim3(Tt / 4, Bb), 128>>>(a_src, a_dst, abias, sn_g, sn_b);
    gx_kernel<<<dim3(ROWS / 32, 3), 256>>>(W_ih, b_ih);
    gru_kernel<<<Bb * Nn / 2, 384>>>(W_hh, b_hh, out);
    tln_kernel<<<ROWS / 8, 256>>>(out, tn_g, tn_b);
}